// round 1
// baseline (speedup 1.0000x reference)
#include <cuda_runtime.h>
#include <cstdint>

#define RBF 128
#define DIM 64
#define WARPS 4
#define TPB (WARPS * 32)
#define TILE_E 16              // edges per warp tile
#define BLK_E (WARPS * TILE_E) // 64 edges per block tile
#define MAXE 1700000
#define GRID_MAIN 304          // 152 SMs * 2 blocks/SM (persistent)

// Shared memory layout (floats):
// sW1 [2][RBF][32]  = 8192
// sW2 [2][DIM][32]  = 4096
// sb1 [64], sb2[64] = 128
// sRbf [WARPS][TILE_E][RBF] = 8192
// sH   [WARPS][TILE_E][DIM] = 4096
#define SMEM_FLOATS (2*RBF*32 + 2*DIM*32 + 2*DIM + WARPS*TILE_E*RBF + WARPS*TILE_E*DIM)
#define SMEM_BYTES (SMEM_FLOATS * 4)

__device__ int g_flag;   // 1 = mask is 1-byte elements, 0 = 4-byte elements
__device__ int g_count;  // number of kept edges
__device__ int g_cidx[MAXE];

// ---------------- packed f32x2 helpers ----------------
__device__ __forceinline__ unsigned long long splat2(float x) {
    unsigned long long r;
    asm("mov.b64 %0, {%1, %1};" : "=l"(r) : "f"(x));
    return r;
}
__device__ __forceinline__ void ffma2(unsigned long long& d,
                                      unsigned long long a,
                                      unsigned long long b) {
    asm("fma.rn.f32x2 %0, %1, %2, %0;" : "+l"(d) : "l"(a), "l"(b));
}
union F2U { unsigned long long u; float2 f; };

// softplus(beta=0.5, threshold=14): matches jnp.where(bx>14, x, 2*logaddexp(0,bx))
__device__ __forceinline__ float softplus_sp(float x) {
    float bx = 0.5f * x;
    if (bx > 14.0f) return x;
    float m = fmaxf(bx, 0.0f);
    return 2.0f * (m + log1pf(expf(-fabsf(bx))));
}

// ---------------- kernel 1: mask dtype detection + counter reset ----------------
// For int32 {0,1} or float32 {0.0,1.0} encodings, bytes at index i%4==1 are
// always 0x00. For a 1-byte bool mask (~28% ones), they are frequently nonzero.
__global__ void detect_kernel(const unsigned char* __restrict__ m, int nElem) {
    __shared__ int s;
    if (threadIdx.x == 0) s = 0;
    __syncthreads();
    int nbytes = 16384;
    if (nElem < nbytes) nbytes = nElem;  // mask buffer >= nElem bytes in all encodings
    int found = 0;
    for (int i = threadIdx.x * 4 + 1; i < nbytes; i += blockDim.x * 4)
        if (m[i]) found = 1;
    if (found) atomicOr(&s, 1);
    __syncthreads();
    if (threadIdx.x == 0) { g_flag = s; g_count = 0; }
}

// ---------------- kernel 2: warp-aggregated stream compaction ----------------
__global__ void compact_kernel(const void* __restrict__ maskp, int E) {
    const int flag = g_flag;
    const unsigned char* m8  = (const unsigned char*)maskp;
    const unsigned int*  m32 = (const unsigned int*)maskp;
    const int lane = threadIdx.x & 31;
    const int stride = gridDim.x * blockDim.x;
    for (int i = blockIdx.x * blockDim.x + threadIdx.x; (i - lane) < E; i += stride) {
        bool p = false;
        if (i < E) p = flag ? (m8[i] != 0) : (m32[i] != 0u);
        unsigned bal = __ballot_sync(0xffffffffu, p);
        if (bal) {
            int pos = 0;
            if (lane == 0) pos = atomicAdd(&g_count, __popc(bal));
            pos = __shfl_sync(0xffffffffu, pos, 0);
            if (p) g_cidx[pos + __popc(bal & ((1u << lane) - 1u))] = i;
        }
    }
}

// ---------------- kernel 3: fused edge MLP + gather-multiply + scatter ----------------
__global__ __launch_bounds__(TPB, 2)
void edge_kernel(const float* __restrict__ rbf, const float* __restrict__ node,
                 const int* __restrict__ src, const int* __restrict__ dst,
                 const float* __restrict__ W1, const float* __restrict__ b1,
                 const float* __restrict__ W2, const float* __restrict__ b2,
                 float* __restrict__ out) {
    extern __shared__ float sm[];
    float* sW1 = sm;                       // [2][RBF][32]
    float* sW2 = sW1 + 2 * RBF * 32;       // [2][DIM][32]
    float* sb1 = sW2 + 2 * DIM * 32;
    float* sb2 = sb1 + DIM;
    float* sRbfAll = sb2 + DIM;            // [WARPS][TILE_E][RBF]
    float* sHAll   = sRbfAll + WARPS * TILE_E * RBF;  // [WARPS][TILE_E][DIM]

    const int tid = threadIdx.x;
    const int wid = tid >> 5;
    const int lane = tid & 31;
    const int er = lane >> 3;   // edge group: owns edges er, er+4, er+8, er+12
    const int cc = lane & 7;    // col group: owns cols cc*4..cc*4+3 in each 32-half

    // Stage weights into shared, split into two 32-col halves (conflict-free b loads)
    for (int i = tid; i < RBF * DIM; i += TPB) {
        int k = i >> 6, c = i & 63;
        sW1[(c >> 5) * (RBF * 32) + k * 32 + (c & 31)] = W1[i];
    }
    for (int i = tid; i < DIM * DIM; i += TPB) {
        int k = i >> 6, c = i & 63;
        sW2[(c >> 5) * (DIM * 32) + k * 32 + (c & 31)] = W2[i];
    }
    if (tid < DIM) { sb1[tid] = b1[tid]; sb2[tid] = b2[tid]; }
    __syncthreads();

    // hoist biases for this lane's columns
    float bs1A[4], bs1B[4], bs2A[4], bs2B[4];
    #pragma unroll
    for (int j = 0; j < 4; j++) {
        bs1A[j] = sb1[cc * 4 + j];  bs1B[j] = sb1[32 + cc * 4 + j];
        bs2A[j] = sb2[cc * 4 + j];  bs2B[j] = sb2[32 + cc * 4 + j];
    }

    float* sRbf = sRbfAll + wid * (TILE_E * RBF);
    float* sH   = sHAll   + wid * (TILE_E * DIM);

    const int cnt = g_count;
    for (long long tile = blockIdx.x; tile * BLK_E < cnt; tile += gridDim.x) {
        const int base = (int)(tile * BLK_E) + wid * TILE_E;
        int v = cnt - base;
        if (v <= 0) continue;
        if (v > TILE_E) v = TILE_E;

        // per-lane edge metadata (lanes 0..15)
        int eid_l = 0, s_l = 0, d_l = 0;
        if (lane < TILE_E && lane < v) {
            eid_l = g_cidx[base + lane];
            s_l = src[eid_l];
            d_l = dst[eid_l];
        }

        // stage rbf rows (512B coalesced per row)
        for (int r = 0; r < v; r++) {
            int eid = __shfl_sync(0xffffffffu, eid_l, r);
            float4 t = *(const float4*)(rbf + (size_t)eid * RBF + lane * 4);
            *(float4*)(sRbf + r * RBF + lane * 4) = t;
        }
        __syncwarp();

        // ---- GEMM1: h1 = rbf @ W1, packed f32x2 ----
        unsigned long long acc[4][4];
        #pragma unroll
        for (int e = 0; e < 4; e++)
            #pragma unroll
            for (int j = 0; j < 4; j++) acc[e][j] = 0ull;

        #pragma unroll 1
        for (int kq = 0; kq < RBF / 4; kq++) {
            float4 a[4];
            #pragma unroll
            for (int e = 0; e < 4; e++)
                a[e] = *(const float4*)(sRbf + (er + e * 4) * RBF + kq * 4);
            #pragma unroll
            for (int kk = 0; kk < 4; kk++) {
                const int k = kq * 4 + kk;
                const ulonglong2 bA = *(const ulonglong2*)(sW1 + k * 32 + cc * 4);
                const ulonglong2 bB = *(const ulonglong2*)(sW1 + RBF * 32 + k * 32 + cc * 4);
                #pragma unroll
                for (int e = 0; e < 4; e++) {
                    unsigned long long s = splat2(((const float*)&a[e])[kk]);
                    ffma2(acc[e][0], s, bA.x);
                    ffma2(acc[e][1], s, bA.y);
                    ffma2(acc[e][2], s, bB.x);
                    ffma2(acc[e][3], s, bB.y);
                }
            }
        }

        // bias + softplus -> stage h1 to shared
        #pragma unroll
        for (int e = 0; e < 4; e++) {
            const int edge = er + e * 4;
            F2U u0, u1, u2, u3;
            u0.u = acc[e][0]; u1.u = acc[e][1]; u2.u = acc[e][2]; u3.u = acc[e][3];
            float4 hA, hB;
            hA.x = softplus_sp(u0.f.x + bs1A[0]);
            hA.y = softplus_sp(u0.f.y + bs1A[1]);
            hA.z = softplus_sp(u1.f.x + bs1A[2]);
            hA.w = softplus_sp(u1.f.y + bs1A[3]);
            hB.x = softplus_sp(u2.f.x + bs1B[0]);
            hB.y = softplus_sp(u2.f.y + bs1B[1]);
            hB.z = softplus_sp(u3.f.x + bs1B[2]);
            hB.w = softplus_sp(u3.f.y + bs1B[3]);
            *(float4*)(sH + edge * DIM + cc * 4) = hA;
            *(float4*)(sH + edge * DIM + 32 + cc * 4) = hB;
        }
        __syncwarp();

        // ---- GEMM2: h2 = h1 @ W2 ----
        unsigned long long acc2[4][4];
        #pragma unroll
        for (int e = 0; e < 4; e++)
            #pragma unroll
            for (int j = 0; j < 4; j++) acc2[e][j] = 0ull;

        #pragma unroll 1
        for (int kq = 0; kq < DIM / 4; kq++) {
            float4 a[4];
            #pragma unroll
            for (int e = 0; e < 4; e++)
                a[e] = *(const float4*)(sH + (er + e * 4) * DIM + kq * 4);
            #pragma unroll
            for (int kk = 0; kk < 4; kk++) {
                const int k = kq * 4 + kk;
                const ulonglong2 bA = *(const ulonglong2*)(sW2 + k * 32 + cc * 4);
                const ulonglong2 bB = *(const ulonglong2*)(sW2 + DIM * 32 + k * 32 + cc * 4);
                #pragma unroll
                for (int e = 0; e < 4; e++) {
                    unsigned long long s = splat2(((const float*)&a[e])[kk]);
                    ffma2(acc2[e][0], s, bA.x);
                    ffma2(acc2[e][1], s, bA.y);
                    ffma2(acc2[e][2], s, bB.x);
                    ffma2(acc2[e][3], s, bB.y);
                }
            }
        }
        __syncwarp();  // all lanes done reading h1 before overwriting

        // h2 = acc2 + b2 -> stage to shared (reuse sH)
        #pragma unroll
        for (int e = 0; e < 4; e++) {
            const int edge = er + e * 4;
            F2U u0, u1, u2, u3;
            u0.u = acc2[e][0]; u1.u = acc2[e][1]; u2.u = acc2[e][2]; u3.u = acc2[e][3];
            float4 hA, hB;
            hA.x = u0.f.x + bs2A[0];  hA.y = u0.f.y + bs2A[1];
            hA.z = u1.f.x + bs2A[2];  hA.w = u1.f.y + bs2A[3];
            hB.x = u2.f.x + bs2B[0];  hB.y = u2.f.y + bs2B[1];
            hB.z = u3.f.x + bs2B[2];  hB.w = u3.f.y + bs2B[3];
            *(float4*)(sH + edge * DIM + cc * 4) = hA;
            *(float4*)(sH + edge * DIM + 32 + cc * 4) = hB;
        }
        __syncwarp();

        // ---- epilogue: msg = new_node[src] * h2, scatter-add to out[dst] ----
        const int half = lane >> 4;          // 2 edges processed per iteration
        const int c4 = (lane & 15) * 4;      // 16 lanes cover 64 cols as float4
        #pragma unroll
        for (int pe = 0; pe < 8; pe++) {
            const int e = pe * 2 + half;
            const int sIdx = __shfl_sync(0xffffffffu, s_l, e);
            const int dIdx = __shfl_sync(0xffffffffu, d_l, e);
            if (e < v) {
                float4 g = *(const float4*)(node + (size_t)sIdx * DIM + c4);
                float4 h = *(const float4*)(sH + e * DIM + c4);
                float* op = out + (size_t)dIdx * DIM + c4;
                atomicAdd(op + 0, g.x * h.x);
                atomicAdd(op + 1, g.y * h.y);
                atomicAdd(op + 2, g.z * h.z);
                atomicAdd(op + 3, g.w * h.w);
            }
        }
    }
}

extern "C" void kernel_launch(void* const* d_in, const int* in_sizes, int n_in,
                              void* d_out, int out_size) {
    const float* rbf  = (const float*)d_in[0];
    const float* node = (const float*)d_in[1];
    const int*   src  = (const int*)d_in[2];
    const int*   dst  = (const int*)d_in[3];
    const void*  mask = d_in[4];
    const float* W1   = (const float*)d_in[5];
    const float* b1   = (const float*)d_in[6];
    const float* W2   = (const float*)d_in[7];
    const float* b2   = (const float*)d_in[8];
    const int E = in_sizes[2];

    cudaMemsetAsync(d_out, 0, (size_t)out_size * sizeof(float));
    detect_kernel<<<1, 256>>>((const unsigned char*)mask, E);
    compact_kernel<<<512, 256>>>(mask, E);

    cudaFuncSetAttribute(edge_kernel, cudaFuncAttributeMaxDynamicSharedMemorySize, SMEM_BYTES);
    edge_kernel<<<GRID_MAIN, TPB, SMEM_BYTES>>>(rbf, node, src, dst, W1, b1, W2, b2,
                                                (float*)d_out);
}

// round 2
// speedup vs baseline: 1.1671x; 1.1671x over previous
#include <cuda_runtime.h>
#include <cstdint>

#define RBFD 128
#define DIM 64
#define TPB 128
#define TILE_E 32
#define RS 132              // padded rbf row stride (floats): conflict-free ldmatrix
#define HS 68               // padded h row stride (floats): conflict-free ldmatrix
#define MAXE 1700000
#define GRID_MAIN 304

__device__ int g_flag;   // 1 = mask is 1-byte elements, 0 = 4-byte elements
__device__ int g_count;  // number of kept edges
__device__ int g_cidx[MAXE];

// ---------------- helpers ----------------
__device__ __forceinline__ uint32_t f2tf(float x) {
    uint32_t r;
    asm("cvt.rna.tf32.f32 %0, %1;" : "=r"(r) : "f"(x));
    return r;
}
__device__ __forceinline__ void cvtA(uint32_t& x) {
    asm("cvt.rna.tf32.f32 %0, %0;" : "+r"(x));
}
__device__ __forceinline__ void ldm4(uint32_t* r, uint32_t addr) {
    asm volatile("ldmatrix.sync.aligned.m8n8.x4.shared.b16 {%0,%1,%2,%3}, [%4];"
                 : "=r"(r[0]), "=r"(r[1]), "=r"(r[2]), "=r"(r[3]) : "r"(addr));
}
__device__ __forceinline__ void mma8(float* c, const uint32_t* a, uint32_t b0, uint32_t b1) {
    asm volatile("mma.sync.aligned.m16n8k8.row.col.f32.tf32.tf32.f32 "
                 "{%0,%1,%2,%3},{%4,%5,%6,%7},{%8,%9},{%0,%1,%2,%3};"
                 : "+f"(c[0]), "+f"(c[1]), "+f"(c[2]), "+f"(c[3])
                 : "r"(a[0]), "r"(a[1]), "r"(a[2]), "r"(a[3]), "r"(b0), "r"(b1));
}
// softplus(beta=0.5, threshold=14): matches jnp.where(bx>14, x, 2*logaddexp(0,bx))
__device__ __forceinline__ float softplus_sp(float x) {
    float bx = 0.5f * x;
    if (bx > 14.0f) return x;
    float m = fmaxf(bx, 0.0f);
    return 2.0f * (m + log1pf(expf(-fabsf(bx))));
}

// ---------------- kernel 1: mask dtype detection + counter reset ----------------
__global__ void detect_kernel(const unsigned char* __restrict__ m, int nElem) {
    __shared__ int s;
    if (threadIdx.x == 0) s = 0;
    __syncthreads();
    int nbytes = 16384;
    if (nElem < nbytes) nbytes = nElem;
    int found = 0;
    for (int i = threadIdx.x * 4 + 1; i < nbytes; i += blockDim.x * 4)
        if (m[i]) found = 1;
    if (found) atomicOr(&s, 1);
    __syncthreads();
    if (threadIdx.x == 0) { g_flag = s; g_count = 0; }
}

// ---------------- kernel 2: zero output + warp-aggregated compaction ----------------
__global__ void compact_kernel(const void* __restrict__ maskp, int E,
                               float* __restrict__ out, int osz) {
    const int stride = gridDim.x * blockDim.x;
    for (int i = blockIdx.x * blockDim.x + threadIdx.x; i < osz; i += stride)
        out[i] = 0.0f;
    const int flag = g_flag;
    const unsigned char* m8  = (const unsigned char*)maskp;
    const unsigned int*  m32 = (const unsigned int*)maskp;
    const int lane = threadIdx.x & 31;
    for (int i = blockIdx.x * blockDim.x + threadIdx.x; (i - lane) < E; i += stride) {
        bool p = false;
        if (i < E) p = flag ? (m8[i] != 0) : (m32[i] != 0u);
        unsigned bal = __ballot_sync(0xffffffffu, p);
        if (bal) {
            int pos = 0;
            if (lane == 0) pos = atomicAdd(&g_count, __popc(bal));
            pos = __shfl_sync(0xffffffffu, pos, 0);
            if (p) g_cidx[pos + __popc(bal & ((1u << lane) - 1u))] = i;
        }
    }
}

// ---------------- kernel 3: tf32 MMA edge MLP + gather-multiply + scatter ----------------
// Block tile = 32 edges. Warp w computes output cols [w*16, w*16+16) for all 32 edges.
// W1/W2 fragments live in registers per warp (loaded once). A via ldmatrix from
// padded shared. Epilogue: red.global.add.v4.f32.
__global__ __launch_bounds__(TPB, 2)
void edge_kernel(const float* __restrict__ rbf, const float* __restrict__ node,
                 const int* __restrict__ src, const int* __restrict__ dst,
                 const float* __restrict__ W1, const float* __restrict__ b1,
                 const float* __restrict__ W2, const float* __restrict__ b2,
                 float* __restrict__ out) {
    __shared__ float sRbf[TILE_E * RS];
    __shared__ float sH1[TILE_E * HS];
    __shared__ float sH2[TILE_E * HS];
    __shared__ int sSrc[TILE_E], sDst[TILE_E], sEid[TILE_E];
    __shared__ float sB1[DIM], sB2[DIM];

    const int tid = threadIdx.x;
    const int wid = tid >> 5;
    const int lane = tid & 31;
    const int kk = lane & 3;       // k-in-group for B frags
    const int nn = lane >> 2;      // n-in-group for B frags

    if (tid < DIM) { sB1[tid] = b1[tid]; sB2[tid] = b2[tid]; }

    // ---- persistent B fragments (tf32) ----
    uint32_t bw1[16][2][2];   // [kstep][ntile][b0/b1]
    #pragma unroll
    for (int ks = 0; ks < 16; ks++)
        #pragma unroll
        for (int j = 0; j < 2; j++) {
            int n = wid * 16 + j * 8 + nn;
            bw1[ks][j][0] = f2tf(W1[(ks * 8 + kk) * DIM + n]);
            bw1[ks][j][1] = f2tf(W1[(ks * 8 + kk + 4) * DIM + n]);
        }
    uint32_t bw2[8][2][2];
    #pragma unroll
    for (int ks = 0; ks < 8; ks++)
        #pragma unroll
        for (int j = 0; j < 2; j++) {
            int n = wid * 16 + j * 8 + nn;
            bw2[ks][j][0] = f2tf(W2[(ks * 8 + kk) * DIM + n]);
            bw2[ks][j][1] = f2tf(W2[(ks * 8 + kk + 4) * DIM + n]);
        }
    __syncthreads();

    float2 bias1[2], bias2[2];
    #pragma unroll
    for (int j = 0; j < 2; j++) {
        int c = wid * 16 + j * 8 + 2 * kk;
        bias1[j] = *(const float2*)&sB1[c];
        bias2[j] = *(const float2*)&sB2[c];
    }

    // ldmatrix per-thread base addresses (x4 layout for tf32 A frags)
    const int rowA = (lane & 7) + ((lane >> 3) & 1) * 8;
    const int colSel = (lane >> 4) * 4;
    const uint32_t rbfBase = (uint32_t)__cvta_generic_to_shared(&sRbf[rowA * RS + colSel]);
    const uint32_t h1Base  = (uint32_t)__cvta_generic_to_shared(&sH1[rowA * HS + colSel]);

    const int cnt = g_count;
    const int ntiles = (cnt + TILE_E - 1) / TILE_E;
    for (int tile = blockIdx.x; tile < ntiles; tile += gridDim.x) {
        const int base = tile * TILE_E;
        const int v = min(TILE_E, cnt - base);
        __syncthreads();   // previous tile fully consumed before overwrite

        if (tid < TILE_E) {
            int idx = g_cidx[base + (tid < v ? tid : 0)];
            sEid[tid] = idx; sSrc[tid] = src[idx]; sDst[tid] = dst[idx];
        }
        __syncthreads();

        // stage rbf rows (cp.async, 16B chunks). thread: edge tid/4, quarter tid%4
        {
            int e = tid >> 2, q = tid & 3;
            const float* g = rbf + (size_t)sEid[e] * RBFD + q * 32;
            uint32_t d = (uint32_t)__cvta_generic_to_shared(&sRbf[e * RS + q * 32]);
            #pragma unroll
            for (int i = 0; i < 8; i++)
                asm volatile("cp.async.cg.shared.global [%0], [%1], 16;"
                             :: "r"(d + i * 16), "l"(g + i * 4));
        }
        asm volatile("cp.async.commit_group;");
        asm volatile("cp.async.wait_group 0;");
        __syncthreads();

        // ---- GEMM1: h1[32,64] = rbf[32,128] @ W1 ----
        float acc[2][2][4];
        #pragma unroll
        for (int m = 0; m < 2; m++)
            #pragma unroll
            for (int j = 0; j < 2; j++)
                #pragma unroll
                for (int r = 0; r < 4; r++) acc[m][j][r] = 0.0f;

        #pragma unroll
        for (int ks = 0; ks < 16; ks++) {
            uint32_t A0[4], A1[4];
            ldm4(A0, rbfBase + ks * 32);
            ldm4(A1, rbfBase + 16 * RS * 4 + ks * 32);
            #pragma unroll
            for (int i = 0; i < 4; i++) { cvtA(A0[i]); cvtA(A1[i]); }
            #pragma unroll
            for (int j = 0; j < 2; j++) {
                mma8(acc[0][j], A0, bw1[ks][j][0], bw1[ks][j][1]);
                mma8(acc[1][j], A1, bw1[ks][j][0], bw1[ks][j][1]);
            }
        }

        // bias + softplus -> sH1
        #pragma unroll
        for (int m = 0; m < 2; m++)
            #pragma unroll
            for (int j = 0; j < 2; j++) {
                int row = m * 16 + (lane >> 2);
                int col = wid * 16 + j * 8 + 2 * kk;
                float2 lo, hi;
                lo.x = softplus_sp(acc[m][j][0] + bias1[j].x);
                lo.y = softplus_sp(acc[m][j][1] + bias1[j].y);
                hi.x = softplus_sp(acc[m][j][2] + bias1[j].x);
                hi.y = softplus_sp(acc[m][j][3] + bias1[j].y);
                *(float2*)&sH1[row * HS + col] = lo;
                *(float2*)&sH1[(row + 8) * HS + col] = hi;
            }
        __syncthreads();

        // ---- GEMM2: h2[32,64] = h1[32,64] @ W2 ----
        float acc2[2][2][4];
        #pragma unroll
        for (int m = 0; m < 2; m++)
            #pragma unroll
            for (int j = 0; j < 2; j++)
                #pragma unroll
                for (int r = 0; r < 4; r++) acc2[m][j][r] = 0.0f;

        #pragma unroll
        for (int ks = 0; ks < 8; ks++) {
            uint32_t A0[4], A1[4];
            ldm4(A0, h1Base + ks * 32);
            ldm4(A1, h1Base + 16 * HS * 4 + ks * 32);
            #pragma unroll
            for (int i = 0; i < 4; i++) { cvtA(A0[i]); cvtA(A1[i]); }
            #pragma unroll
            for (int j = 0; j < 2; j++) {
                mma8(acc2[0][j], A0, bw2[ks][j][0], bw2[ks][j][1]);
                mma8(acc2[1][j], A1, bw2[ks][j][0], bw2[ks][j][1]);
            }
        }

        // bias -> sH2
        #pragma unroll
        for (int m = 0; m < 2; m++)
            #pragma unroll
            for (int j = 0; j < 2; j++) {
                int row = m * 16 + (lane >> 2);
                int col = wid * 16 + j * 8 + 2 * kk;
                float2 lo, hi;
                lo.x = acc2[m][j][0] + bias2[j].x;
                lo.y = acc2[m][j][1] + bias2[j].y;
                hi.x = acc2[m][j][2] + bias2[j].x;
                hi.y = acc2[m][j][3] + bias2[j].y;
                *(float2*)&sH2[row * HS + col] = lo;
                *(float2*)&sH2[(row + 8) * HS + col] = hi;
            }
        __syncthreads();

        // ---- epilogue: msg = node[src] * h2, vectorized scatter-add ----
        {
            int e = tid >> 2, q = tid & 3;
            if (e < v) {
                const float4* np = (const float4*)(node + (size_t)sSrc[e] * DIM + q * 16);
                float* op = out + (size_t)sDst[e] * DIM + q * 16;
                #pragma unroll
                for (int i = 0; i < 4; i++) {
                    float4 gg = np[i];
                    float4 hh = *(const float4*)&sH2[e * HS + q * 16 + i * 4];
                    asm volatile("red.global.add.v4.f32 [%0], {%1,%2,%3,%4};"
                                 :: "l"(op + i * 4),
                                    "f"(gg.x * hh.x), "f"(gg.y * hh.y),
                                    "f"(gg.z * hh.z), "f"(gg.w * hh.w)
                                 : "memory");
                }
            }
        }
    }
}

extern "C" void kernel_launch(void* const* d_in, const int* in_sizes, int n_in,
                              void* d_out, int out_size) {
    const float* rbf  = (const float*)d_in[0];
    const float* node = (const float*)d_in[1];
    const int*   src  = (const int*)d_in[2];
    const int*   dst  = (const int*)d_in[3];
    const void*  mask = d_in[4];
    const float* W1   = (const float*)d_in[5];
    const float* b1   = (const float*)d_in[6];
    const float* W2   = (const float*)d_in[7];
    const float* b2   = (const float*)d_in[8];
    const int E = in_sizes[2];

    detect_kernel<<<1, 256>>>((const unsigned char*)mask, E);
    compact_kernel<<<512, 256>>>(mask, E, (float*)d_out, out_size);
    edge_kernel<<<GRID_MAIN, TPB>>>(rbf, node, src, dst, W1, b1, W2, b2, (float*)d_out);
}

// round 3
// speedup vs baseline: 1.7242x; 1.4774x over previous
#include <cuda_runtime.h>
#include <cstdint>

#define RBFD 128
#define DIM 64
#define TPB 128
#define TILE_E 32
#define RS 132              // padded rbf row stride (floats)
#define HS 68               // padded h row stride (floats)
#define NS 68               // padded node row stride (floats)
#define MAXE 1700000
#define GRID_MAIN 304

#define SMEM_FLOATS (2*TILE_E*RS + 2*TILE_E*NS + 2*TILE_E*HS + 2*DIM)
#define SMEM_BYTES  (SMEM_FLOATS*4 + 3*2*TILE_E*4)

__device__ int g_flag;
__device__ int g_count;
__device__ int g_cidx[MAXE];

// ---------------- helpers ----------------
__device__ __forceinline__ uint32_t f2tf(float x) {
    uint32_t r;
    asm("cvt.rna.tf32.f32 %0, %1;" : "=r"(r) : "f"(x));
    return r;
}
__device__ __forceinline__ void cvtA(uint32_t& x) {
    asm("cvt.rna.tf32.f32 %0, %0;" : "+r"(x));
}
__device__ __forceinline__ void ldm4(uint32_t* r, uint32_t addr) {
    asm volatile("ldmatrix.sync.aligned.m8n8.x4.shared.b16 {%0,%1,%2,%3}, [%4];"
                 : "=r"(r[0]), "=r"(r[1]), "=r"(r[2]), "=r"(r[3]) : "r"(addr));
}
__device__ __forceinline__ void mma8(float* c, const uint32_t* a, uint32_t b0, uint32_t b1) {
    asm volatile("mma.sync.aligned.m16n8k8.row.col.f32.tf32.tf32.f32 "
                 "{%0,%1,%2,%3},{%4,%5,%6,%7},{%8,%9},{%0,%1,%2,%3};"
                 : "+f"(c[0]), "+f"(c[1]), "+f"(c[2]), "+f"(c[3])
                 : "r"(a[0]), "r"(a[1]), "r"(a[2]), "r"(a[3]), "r"(b0), "r"(b1));
}
__device__ __forceinline__ void cpa16(uint32_t d, const void* s) {
    asm volatile("cp.async.cg.shared.global [%0], [%1], 16;" :: "r"(d), "l"(s));
}
__device__ __forceinline__ float softplus_sp(float x) {
    float bx = 0.5f * x;
    if (bx > 14.0f) return x;
    float m = fmaxf(bx, 0.0f);
    return 2.0f * (m + log1pf(expf(-fabsf(bx))));
}

// ---------------- kernel 1: mask dtype detection + counter reset ----------------
__global__ void detect_kernel(const unsigned char* __restrict__ m, int nElem) {
    __shared__ int s;
    if (threadIdx.x == 0) s = 0;
    __syncthreads();
    int nbytes = 16384;
    if (nElem < nbytes) nbytes = nElem;
    int found = 0;
    for (int i = threadIdx.x * 4 + 1; i < nbytes; i += blockDim.x * 4)
        if (m[i]) found = 1;
    if (found) atomicOr(&s, 1);
    __syncthreads();
    if (threadIdx.x == 0) { g_flag = s; g_count = 0; }
}

// ---------------- kernel 2: zero output + warp-aggregated compaction ----------------
__global__ void compact_kernel(const void* __restrict__ maskp, int E,
                               float* __restrict__ out, int osz) {
    const int stride = gridDim.x * blockDim.x;
    for (int i = blockIdx.x * blockDim.x + threadIdx.x; i < osz; i += stride)
        out[i] = 0.0f;
    const int flag = g_flag;
    const unsigned char* m8  = (const unsigned char*)maskp;
    const unsigned int*  m32 = (const unsigned int*)maskp;
    const int lane = threadIdx.x & 31;
    for (int i = blockIdx.x * blockDim.x + threadIdx.x; (i - lane) < E; i += stride) {
        bool p = false;
        if (i < E) p = flag ? (m8[i] != 0) : (m32[i] != 0u);
        unsigned bal = __ballot_sync(0xffffffffu, p);
        if (bal) {
            int pos = 0;
            if (lane == 0) pos = atomicAdd(&g_count, __popc(bal));
            pos = __shfl_sync(0xffffffffu, pos, 0);
            if (p) g_cidx[pos + __popc(bal & ((1u << lane) - 1u))] = i;
        }
    }
}

// ---------------- kernel 3: pipelined tf32 MMA edge MLP ----------------
__global__ __launch_bounds__(TPB, 2)
void edge_kernel(const float* __restrict__ rbf, const float* __restrict__ node,
                 const int* __restrict__ src, const int* __restrict__ dst,
                 const float* __restrict__ W1, const float* __restrict__ b1,
                 const float* __restrict__ W2, const float* __restrict__ b2,
                 float* __restrict__ out) {
    extern __shared__ float sm[];
    float* sRbf  = sm;                       // [2][TILE_E*RS]
    float* sNode = sRbf + 2 * TILE_E * RS;   // [2][TILE_E*NS]
    float* sH1   = sNode + 2 * TILE_E * NS;  // [TILE_E*HS]
    float* sH2   = sH1 + TILE_E * HS;        // [TILE_E*HS]
    float* sB1   = sH2 + TILE_E * HS;
    float* sB2   = sB1 + DIM;
    int* sEid = (int*)(sB2 + DIM);           // [2][TILE_E]
    int* sSrc = sEid + 2 * TILE_E;
    int* sDst = sSrc + 2 * TILE_E;

    const int tid = threadIdx.x;
    const int wid = tid >> 5;
    const int lane = tid & 31;
    const int kk = lane & 3;
    const int nn = lane >> 2;
    const int eE = tid >> 2;    // edge owned for staging/epilogue
    const int qQ = tid & 3;     // quarter owned

    if (tid < DIM) { sB1[tid] = b1[tid]; sB2[tid] = b2[tid]; }

    // persistent B fragments (tf32) in registers
    uint32_t bw1[16][2][2];
    #pragma unroll
    for (int ks = 0; ks < 16; ks++)
        #pragma unroll
        for (int j = 0; j < 2; j++) {
            int n = wid * 16 + j * 8 + nn;
            bw1[ks][j][0] = f2tf(W1[(ks * 8 + kk) * DIM + n]);
            bw1[ks][j][1] = f2tf(W1[(ks * 8 + kk + 4) * DIM + n]);
        }
    uint32_t bw2[8][2][2];
    #pragma unroll
    for (int ks = 0; ks < 8; ks++)
        #pragma unroll
        for (int j = 0; j < 2; j++) {
            int n = wid * 16 + j * 8 + nn;
            bw2[ks][j][0] = f2tf(W2[(ks * 8 + kk) * DIM + n]);
            bw2[ks][j][1] = f2tf(W2[(ks * 8 + kk + 4) * DIM + n]);
        }
    __syncthreads();

    float2 bias1[2], bias2[2];
    #pragma unroll
    for (int j = 0; j < 2; j++) {
        int c = wid * 16 + j * 8 + 2 * kk;
        bias1[j] = *(const float2*)&sB1[c];
        bias2[j] = *(const float2*)&sB2[c];
    }

    const int rowA = (lane & 7) + ((lane >> 3) & 1) * 8;
    const int colSel = (lane >> 4) * 4;
    const uint32_t h1Base = (uint32_t)__cvta_generic_to_shared(&sH1[rowA * HS + colSel]);

    const int cnt = g_count;
    const int ntiles = (cnt + TILE_E - 1) / TILE_E;

    // ---- stage helpers (inline lambdas) ----
    auto load_meta = [&](int t, int b) {
        if (tid < TILE_E) {
            int base = t * TILE_E;
            int v = cnt - base; if (v > TILE_E) v = TILE_E;
            int idx = g_cidx[base + (tid < v ? tid : 0)];
            sEid[b * TILE_E + tid] = idx;
            sSrc[b * TILE_E + tid] = src[idx];
            sDst[b * TILE_E + tid] = dst[idx];
        }
    };
    auto issue_async = [&](int b) {
        // rbf: 8 x 16B per thread
        const float* g = rbf + (size_t)sEid[b * TILE_E + eE] * RBFD + qQ * 32;
        uint32_t d = (uint32_t)__cvta_generic_to_shared(&sRbf[b * TILE_E * RS + eE * RS + qQ * 32]);
        #pragma unroll
        for (int i = 0; i < 8; i++) cpa16(d + i * 16, g + i * 4);
        // node[src]: 4 x 16B per thread
        const float* gn = node + (size_t)sSrc[b * TILE_E + eE] * DIM + qQ * 16;
        uint32_t dn = (uint32_t)__cvta_generic_to_shared(&sNode[b * TILE_E * NS + eE * NS + qQ * 16]);
        #pragma unroll
        for (int i = 0; i < 4; i++) cpa16(dn + i * 16, gn + i * 4);
        asm volatile("cp.async.commit_group;");
    };

    // ---- prologue: prefetch first tile ----
    int t0 = blockIdx.x;
    if (t0 < ntiles) {
        load_meta(t0, 0);
        __syncthreads();
        issue_async(0);
    }

    int it = 0;
    for (int t = t0; t < ntiles; t += gridDim.x, it++) {
        const int p = it & 1;
        const int tn = t + gridDim.x;
        const int v = min(TILE_E, cnt - t * TILE_E);

        __syncthreads();                       // prior epilogue done before meta[1-p] overwrite
        if (tn < ntiles) load_meta(tn, 1 - p);
        asm volatile("cp.async.wait_group 0;");
        __syncthreads();                       // buffer p + next meta visible
        if (tn < ntiles) issue_async(1 - p);   // overlaps with compute below

        const uint32_t rbfBase = (uint32_t)__cvta_generic_to_shared(
            &sRbf[p * TILE_E * RS + rowA * RS + colSel]);

        // ---- GEMM1 ----
        float acc[2][2][4];
        #pragma unroll
        for (int m = 0; m < 2; m++)
            #pragma unroll
            for (int j = 0; j < 2; j++)
                #pragma unroll
                for (int r = 0; r < 4; r++) acc[m][j][r] = 0.0f;

        #pragma unroll
        for (int ks = 0; ks < 16; ks++) {
            uint32_t A0[4], A1[4];
            ldm4(A0, rbfBase + ks * 32);
            ldm4(A1, rbfBase + 16 * RS * 4 + ks * 32);
            #pragma unroll
            for (int i = 0; i < 4; i++) { cvtA(A0[i]); cvtA(A1[i]); }
            #pragma unroll
            for (int j = 0; j < 2; j++) {
                mma8(acc[0][j], A0, bw1[ks][j][0], bw1[ks][j][1]);
                mma8(acc[1][j], A1, bw1[ks][j][0], bw1[ks][j][1]);
            }
        }

        #pragma unroll
        for (int m = 0; m < 2; m++)
            #pragma unroll
            for (int j = 0; j < 2; j++) {
                int row = m * 16 + (lane >> 2);
                int col = wid * 16 + j * 8 + 2 * kk;
                float2 lo, hi;
                lo.x = softplus_sp(acc[m][j][0] + bias1[j].x);
                lo.y = softplus_sp(acc[m][j][1] + bias1[j].y);
                hi.x = softplus_sp(acc[m][j][2] + bias1[j].x);
                hi.y = softplus_sp(acc[m][j][3] + bias1[j].y);
                *(float2*)&sH1[row * HS + col] = lo;
                *(float2*)&sH1[(row + 8) * HS + col] = hi;
            }
        __syncthreads();

        // ---- GEMM2 ----
        float acc2[2][2][4];
        #pragma unroll
        for (int m = 0; m < 2; m++)
            #pragma unroll
            for (int j = 0; j < 2; j++)
                #pragma unroll
                for (int r = 0; r < 4; r++) acc2[m][j][r] = 0.0f;

        #pragma unroll
        for (int ks = 0; ks < 8; ks++) {
            uint32_t A0[4], A1[4];
            ldm4(A0, h1Base + ks * 32);
            ldm4(A1, h1Base + 16 * HS * 4 + ks * 32);
            #pragma unroll
            for (int i = 0; i < 4; i++) { cvtA(A0[i]); cvtA(A1[i]); }
            #pragma unroll
            for (int j = 0; j < 2; j++) {
                mma8(acc2[0][j], A0, bw2[ks][j][0], bw2[ks][j][1]);
                mma8(acc2[1][j], A1, bw2[ks][j][0], bw2[ks][j][1]);
            }
        }

        #pragma unroll
        for (int m = 0; m < 2; m++)
            #pragma unroll
            for (int j = 0; j < 2; j++) {
                int row = m * 16 + (lane >> 2);
                int col = wid * 16 + j * 8 + 2 * kk;
                float2 lo, hi;
                lo.x = acc2[m][j][0] + bias2[j].x;
                lo.y = acc2[m][j][1] + bias2[j].y;
                hi.x = acc2[m][j][2] + bias2[j].x;
                hi.y = acc2[m][j][3] + bias2[j].y;
                *(float2*)&sH2[row * HS + col] = lo;
                *(float2*)&sH2[(row + 8) * HS + col] = hi;
            }
        __syncthreads();

        // ---- epilogue: msg = node[src] * h2 from shared, scatter-add ----
        if (eE < v) {
            float* op = out + (size_t)sDst[p * TILE_E + eE] * DIM + qQ * 16;
            const float* sn = &sNode[p * TILE_E * NS + eE * NS + qQ * 16];
            const float* sh = &sH2[eE * HS + qQ * 16];
            #pragma unroll
            for (int i = 0; i < 4; i++) {
                float4 gg = *(const float4*)(sn + i * 4);
                float4 hh = *(const float4*)(sh + i * 4);
                asm volatile("red.global.add.v4.f32 [%0], {%1,%2,%3,%4};"
                             :: "l"(op + i * 4),
                                "f"(gg.x * hh.x), "f"(gg.y * hh.y),
                                "f"(gg.z * hh.z), "f"(gg.w * hh.w)
                             : "memory");
            }
        }
    }
}

extern "C" void kernel_launch(void* const* d_in, const int* in_sizes, int n_in,
                              void* d_out, int out_size) {
    const float* rbf  = (const float*)d_in[0];
    const float* node = (const float*)d_in[1];
    const int*   src  = (const int*)d_in[2];
    const int*   dst  = (const int*)d_in[3];
    const void*  mask = d_in[4];
    const float* W1   = (const float*)d_in[5];
    const float* b1   = (const float*)d_in[6];
    const float* W2   = (const float*)d_in[7];
    const float* b2   = (const float*)d_in[8];
    const int E = in_sizes[2];

    detect_kernel<<<1, 256>>>((const unsigned char*)mask, E);
    compact_kernel<<<512, 256>>>(mask, E, (float*)d_out, out_size);
    cudaFuncSetAttribute(edge_kernel, cudaFuncAttributeMaxDynamicSharedMemorySize, SMEM_BYTES);
    edge_kernel<<<GRID_MAIN, TPB, SMEM_BYTES>>>(rbf, node, src, dst, W1, b1, W2, b2,
                                                (float*)d_out);
}

// round 5
// speedup vs baseline: 1.9781x; 1.1472x over previous
#include <cuda_runtime.h>
#include <cstdint>

#define RBFD 128
#define DIM 64
#define TPB 128
#define TILE_E 32
#define RS 132              // padded rbf row stride (floats)
#define HS 68               // padded h row stride (floats)
#define NS 68               // padded node row stride (floats)
#define MAXE 1700000
#define GRID_MAIN 304

#define SMEM_FLOATS (2*TILE_E*RS + 2*TILE_E*NS + 2*TILE_E*HS + 2*DIM)
#define SMEM_BYTES  (SMEM_FLOATS*4 + 2*TILE_E*4)

__device__ int g_flag;
__device__ int g_count;
__device__ int g_cidx[MAXE];

// ---------------- helpers ----------------
__device__ __forceinline__ uint32_t f2tf(float x) {
    uint32_t r;
    asm("cvt.rna.tf32.f32 %0, %1;" : "=r"(r) : "f"(x));
    return r;
}
__device__ __forceinline__ void cvtA(uint32_t& x) {
    asm("cvt.rna.tf32.f32 %0, %0;" : "+r"(x));
}
__device__ __forceinline__ void ldm4(uint32_t* r, uint32_t addr) {
    asm volatile("ldmatrix.sync.aligned.m8n8.x4.shared.b16 {%0,%1,%2,%3}, [%4];"
                 : "=r"(r[0]), "=r"(r[1]), "=r"(r[2]), "=r"(r[3]) : "r"(addr));
}
__device__ __forceinline__ void mma8(float* c, const uint32_t* a, uint32_t b0, uint32_t b1) {
    asm volatile("mma.sync.aligned.m16n8k8.row.col.f32.tf32.tf32.f32 "
                 "{%0,%1,%2,%3},{%4,%5,%6,%7},{%8,%9},{%0,%1,%2,%3};"
                 : "+f"(c[0]), "+f"(c[1]), "+f"(c[2]), "+f"(c[3])
                 : "r"(a[0]), "r"(a[1]), "r"(a[2]), "r"(a[3]), "r"(b0), "r"(b1));
}
__device__ __forceinline__ void cpa16(uint32_t d, const void* s) {
    asm volatile("cp.async.cg.shared.global [%0], [%1], 16;" :: "r"(d), "l"(s));
}
__device__ __forceinline__ float softplus_sp(float x) {
    float bx = 0.5f * x;
    if (bx > 14.0f) return x;
    float m = fmaxf(bx, 0.0f);
    return 2.0f * (m + log1pf(expf(-fabsf(bx))));
}

// ---------------- kernel 1: mask dtype detection + counter reset ----------------
__global__ void detect_kernel(const unsigned char* __restrict__ m, int nElem) {
    __shared__ int s;
    if (threadIdx.x == 0) s = 0;
    __syncthreads();
    int nbytes = 16384;
    if (nElem < nbytes) nbytes = nElem;
    int found = 0;
    for (int i = threadIdx.x * 4 + 1; i < nbytes; i += blockDim.x * 4)
        if (m[i]) found = 1;
    if (found) atomicOr(&s, 1);
    __syncthreads();
    if (threadIdx.x == 0) { g_flag = s; g_count = 0; }
}

// ---------------- kernel 2: zero output + warp-aggregated compaction ----------------
__global__ void compact_kernel(const void* __restrict__ maskp, int E,
                               float* __restrict__ out, int osz) {
    const int stride = gridDim.x * blockDim.x;
    for (int i = blockIdx.x * blockDim.x + threadIdx.x; i < osz; i += stride)
        out[i] = 0.0f;
    const int flag = g_flag;
    const unsigned char* m8  = (const unsigned char*)maskp;
    const unsigned int*  m32 = (const unsigned int*)maskp;
    const int lane = threadIdx.x & 31;
    for (int i = blockIdx.x * blockDim.x + threadIdx.x; (i - lane) < E; i += stride) {
        bool p = false;
        if (i < E) p = flag ? (m8[i] != 0) : (m32[i] != 0u);
        unsigned bal = __ballot_sync(0xffffffffu, p);
        if (bal) {
            int pos = 0;
            if (lane == 0) pos = atomicAdd(&g_count, __popc(bal));
            pos = __shfl_sync(0xffffffffu, pos, 0);
            if (p) g_cidx[pos + __popc(bal & ((1u << lane) - 1u))] = i;
        }
    }
}

// ---------------- kernel 3: deeply pipelined tf32 MMA edge MLP ----------------
__global__ __launch_bounds__(TPB, 2)
void edge_kernel(const float* __restrict__ rbf, const float* __restrict__ node,
                 const int* __restrict__ src, const int* __restrict__ dst,
                 const float* __restrict__ W1, const float* __restrict__ b1,
                 const float* __restrict__ W2, const float* __restrict__ b2,
                 float* __restrict__ out, int E) {
    extern __shared__ float sm[];
    float* sRbf  = sm;                       // [2][TILE_E*RS]
    float* sNode = sRbf + 2 * TILE_E * RS;   // [2][TILE_E*NS]
    float* sH1   = sNode + 2 * TILE_E * NS;  // [TILE_E*HS]
    float* sH2   = sH1 + TILE_E * HS;        // [TILE_E*HS]
    float* sB1   = sH2 + TILE_E * HS;
    float* sB2   = sB1 + DIM;
    int*   sCid  = (int*)(sB2 + DIM);        // [2][TILE_E] cidx ping-pong

    const int tid = threadIdx.x;
    const int wid = tid >> 5;
    const int lane = tid & 31;
    const int kk = lane & 3;
    const int nn = lane >> 2;
    const int eE = tid >> 2;    // edge owned for staging/epilogue
    const int qQ = tid & 3;     // quarter owned

    if (tid < DIM) { sB1[tid] = b1[tid]; sB2[tid] = b2[tid]; }

    // persistent B fragments (tf32) in registers
    uint32_t bw1[16][2][2];
    #pragma unroll
    for (int ks = 0; ks < 16; ks++)
        #pragma unroll
        for (int j = 0; j < 2; j++) {
            int n = wid * 16 + j * 8 + nn;
            bw1[ks][j][0] = f2tf(W1[(ks * 8 + kk) * DIM + n]);
            bw1[ks][j][1] = f2tf(W1[(ks * 8 + kk + 4) * DIM + n]);
        }
    uint32_t bw2[8][2][2];
    #pragma unroll
    for (int ks = 0; ks < 8; ks++)
        #pragma unroll
        for (int j = 0; j < 2; j++) {
            int n = wid * 16 + j * 8 + nn;
            bw2[ks][j][0] = f2tf(W2[(ks * 8 + kk) * DIM + n]);
            bw2[ks][j][1] = f2tf(W2[(ks * 8 + kk + 4) * DIM + n]);
        }
    __syncthreads();

    float2 bias1[2], bias2[2];
    #pragma unroll
    for (int j = 0; j < 2; j++) {
        int c = wid * 16 + j * 8 + 2 * kk;
        bias1[j] = *(const float2*)&sB1[c];
        bias2[j] = *(const float2*)&sB2[c];
    }

    const int rowA = (lane & 7) + ((lane >> 3) & 1) * 8;
    const int colSel = (lane >> 4) * 4;
    const uint32_t h1Base = (uint32_t)__cvta_generic_to_shared(&sH1[rowA * HS + colSel]);

    const int cnt = g_count;
    if (cnt == 0) return;
    const int ntiles = (cnt + TILE_E - 1) / TILE_E;
    const int G = gridDim.x;
    const int t0 = blockIdx.x;
    if (t0 >= ntiles) return;

    auto issue_rbf = [&](int b, int c) {
        const float* g = rbf + (size_t)c * RBFD + qQ * 32;
        uint32_t d = (uint32_t)__cvta_generic_to_shared(
            &sRbf[b * TILE_E * RS + eE * RS + qQ * 32]);
        #pragma unroll
        for (int i = 0; i < 8; i++) cpa16(d + i * 16, g + i * 4);
    };
    auto issue_node = [&](int b, int s) {
        const float* gn = node + (size_t)s * DIM + qQ * 16;
        uint32_t dn = (uint32_t)__cvta_generic_to_shared(
            &sNode[b * TILE_E * NS + eE * NS + qQ * 16]);
        #pragma unroll
        for (int i = 0; i < 4; i++) cpa16(dn + i * 16, gn + i * 4);
    };

    // ---- prologue: tile t0 fully staged, cidx[t0+G] staged ----
    if (tid < TILE_E) {
        int i0 = t0 * TILE_E + tid;
        if (i0 > cnt - 1) i0 = cnt - 1;
        sCid[tid] = g_cidx[i0];
        int t1 = t0 + G;
        if (t1 < ntiles) {
            int i1 = t1 * TILE_E + tid;
            if (i1 > cnt - 1) i1 = cnt - 1;
            sCid[TILE_E + tid] = g_cidx[i1];
        } else {
            sCid[TILE_E + tid] = 0;
        }
    }
    __syncthreads();
    int d_cur;
    {
        int c0 = sCid[eE];
        if (c0 < 0) c0 = 0; else if (c0 > E - 1) c0 = E - 1;
        issue_rbf(0, c0);
        int s0 = src[c0];
        d_cur = dst[c0];
        issue_node(0, s0);
        asm volatile("cp.async.commit_group;");
    }

    int it = 0;
    for (int t = t0; t < ntiles; t += G, it++) {
        const int p = it & 1;
        const int tn = t + G;
        const int v = min(TILE_E, cnt - t * TILE_E);

        asm volatile("cp.async.wait_group 0;");
        __syncthreads();   // tile-t buffers + cidx[tn] visible; prev epilogue done

        // ---- stage tile tn: rbf now, src/dst gathers in flight, node after GEMM1
        int s_next = 0, d_next = 0;
        const bool haveN = (tn < ntiles);
        if (haveN) {
            int cN = sCid[((it + 1) & 1) * TILE_E + eE];
            if (cN < 0) cN = 0; else if (cN > E - 1) cN = E - 1;
            issue_rbf(1 - p, cN);
            s_next = src[cN];          // L2 gather, consumed after GEMM1
            d_next = dst[cN];
        }
        // prefetch cidx for t+2G into slot p (consumed two iterations later)
        if (tid < 8) {
            int t2 = t + 2 * G;
            if (t2 < ntiles) {
                long long i2 = (long long)t2 * TILE_E + tid * 4;
                if (i2 > (long long)MAXE - 4) i2 = (long long)MAXE - 4;
                uint32_t dci = (uint32_t)__cvta_generic_to_shared(&sCid[p * TILE_E + tid * 4]);
                cpa16(dci, &g_cidx[i2]);
            }
        }
        asm volatile("cp.async.commit_group;");

        const uint32_t rbfBase = (uint32_t)__cvta_generic_to_shared(
            &sRbf[p * TILE_E * RS + rowA * RS + colSel]);

        // ---- GEMM1 ----
        float acc[2][2][4];
        #pragma unroll
        for (int m = 0; m < 2; m++)
            #pragma unroll
            for (int j = 0; j < 2; j++)
                #pragma unroll
                for (int r = 0; r < 4; r++) acc[m][j][r] = 0.0f;

        #pragma unroll
        for (int ks = 0; ks < 16; ks++) {
            uint32_t A0[4], A1[4];
            ldm4(A0, rbfBase + ks * 32);
            ldm4(A1, rbfBase + 16 * RS * 4 + ks * 32);
            #pragma unroll
            for (int i = 0; i < 4; i++) { cvtA(A0[i]); cvtA(A1[i]); }
            #pragma unroll
            for (int j = 0; j < 2; j++) {
                mma8(acc[0][j], A0, bw1[ks][j][0], bw1[ks][j][1]);
                mma8(acc[1][j], A1, bw1[ks][j][0], bw1[ks][j][1]);
            }
        }

        // bias + softplus, rounded to tf32 at store (saves cvt in GEMM2)
        #pragma unroll
        for (int m = 0; m < 2; m++)
            #pragma unroll
            for (int j = 0; j < 2; j++) {
                int row = m * 16 + (lane >> 2);
                int col = wid * 16 + j * 8 + 2 * kk;
                uint2 lo, hi;
                lo.x = f2tf(softplus_sp(acc[m][j][0] + bias1[j].x));
                lo.y = f2tf(softplus_sp(acc[m][j][1] + bias1[j].y));
                hi.x = f2tf(softplus_sp(acc[m][j][2] + bias1[j].x));
                hi.y = f2tf(softplus_sp(acc[m][j][3] + bias1[j].y));
                *(uint2*)&sH1[row * HS + col] = lo;
                *(uint2*)&sH1[(row + 8) * HS + col] = hi;
            }

        // node gather for tn: src values have landed during GEMM1
        if (haveN) issue_node(1 - p, s_next);
        asm volatile("cp.async.commit_group;");
        __syncthreads();

        // ---- GEMM2 (A already tf32 — no cvt) ----
        float acc2[2][2][4];
        #pragma unroll
        for (int m = 0; m < 2; m++)
            #pragma unroll
            for (int j = 0; j < 2; j++)
                #pragma unroll
                for (int r = 0; r < 4; r++) acc2[m][j][r] = 0.0f;

        #pragma unroll
        for (int ks = 0; ks < 8; ks++) {
            uint32_t A0[4], A1[4];
            ldm4(A0, h1Base + ks * 32);
            ldm4(A1, h1Base + 16 * HS * 4 + ks * 32);
            #pragma unroll
            for (int j = 0; j < 2; j++) {
                mma8(acc2[0][j], A0, bw2[ks][j][0], bw2[ks][j][1]);
                mma8(acc2[1][j], A1, bw2[ks][j][0], bw2[ks][j][1]);
            }
        }

        #pragma unroll
        for (int m = 0; m < 2; m++)
            #pragma unroll
            for (int j = 0; j < 2; j++) {
                int row = m * 16 + (lane >> 2);
                int col = wid * 16 + j * 8 + 2 * kk;
                float2 lo, hi;
                lo.x = acc2[m][j][0] + bias2[j].x;
                lo.y = acc2[m][j][1] + bias2[j].y;
                hi.x = acc2[m][j][2] + bias2[j].x;
                hi.y = acc2[m][j][3] + bias2[j].y;
                *(float2*)&sH2[row * HS + col] = lo;
                *(float2*)&sH2[(row + 8) * HS + col] = hi;
            }
        __syncthreads();

        // ---- epilogue: msg = node[src] * h2 from shared, scatter-add ----
        if (eE < v) {
            float* op = out + (size_t)d_cur * DIM + qQ * 16;
            const float* sn = &sNode[p * TILE_E * NS + eE * NS + qQ * 16];
            const float* sh = &sH2[eE * HS + qQ * 16];
            #pragma unroll
            for (int i = 0; i < 4; i++) {
                float4 gg = *(const float4*)(sn + i * 4);
                float4 hh = *(const float4*)(sh + i * 4);
                asm volatile("red.global.add.v4.f32 [%0], {%1,%2,%3,%4};"
                             :: "l"(op + i * 4),
                                "f"(gg.x * hh.x), "f"(gg.y * hh.y),
                                "f"(gg.z * hh.z), "f"(gg.w * hh.w)
                             : "memory");
            }
        }
        d_cur = d_next;
    }
}

extern "C" void kernel_launch(void* const* d_in, const int* in_sizes, int n_in,
                              void* d_out, int out_size) {
    const float* rbf  = (const float*)d_in[0];
    const float* node = (const float*)d_in[1];
    const int*   src  = (const int*)d_in[2];
    const int*   dst  = (const int*)d_in[3];
    const void*  mask = d_in[4];
    const float* W1   = (const float*)d_in[5];
    const float* b1   = (const float*)d_in[6];
    const float* W2   = (const float*)d_in[7];
    const float* b2   = (const float*)d_in[8];
    const int E = in_sizes[2];

    detect_kernel<<<1, 256>>>((const unsigned char*)mask, E);
    compact_kernel<<<512, 256>>>(mask, E, (float*)d_out, out_size);
    cudaFuncSetAttribute(edge_kernel, cudaFuncAttributeMaxDynamicSharedMemorySize, SMEM_BYTES);
    edge_kernel<<<GRID_MAIN, TPB, SMEM_BYTES>>>(rbf, node, src, dst, W1, b1, W2, b2,
                                                (float*)d_out, E);
}